// round 12
// baseline (speedup 1.0000x reference)
#include <cuda_runtime.h>
#include <cuda_bf16.h>

// Problem constants (fixed by setup_inputs)
#define BB 32      // batch
#define TT 2048    // timesteps
#define HH 512     // hidden per direction
#define DH 1024    // D*H
#define CC 1024    // input feature size
#define NWARP 64   // fused-pass warps per batch
#define WT (TT / NWARP)  // 32 timesteps per warp
#define NPART 16   // merged partials per batch (one per block)
#define SSTAGES 3  // smem ring stages per warp (1 timestep = 4KB each)
#define PRE 2      // stages kept in flight
#define KSPLIT 4   // qproj K-split (k-slice of 256 per block)

typedef unsigned long long u64;

// ---------------- scratch (no runtime allocation allowed) ----------------
__device__ float g_qpart[KSPLIT][BB * DH];         // split-K query partials
__device__ float g_scores[BB * TT];                // raw (pre-softmax) scores
__device__ float g_pm[BB * NPART];                 // per-block running max
__device__ float g_pl[BB * NPART];                 // per-block running sum
__device__ float g_pa[(size_t)BB * NPART * DH];    // per-block weighted accum (2 MB)
__device__ unsigned g_cnt[BB];                     // producer counters (self-resetting)

// packed f32x2 fma helpers (Blackwell FFMA2 — PTX-only)
__device__ __forceinline__ void ffma2(u64& d, u64 a, u64 b) {
  asm("fma.rn.f32x2 %0, %1, %2, %0;" : "+l"(d) : "l"(a), "l"(b));
}
__device__ __forceinline__ float2 u2f(u64 v) {
  float2 f;
  asm("mov.b64 {%0, %1}, %2;" : "=f"(f.x), "=f"(f.y) : "l"(v));
  return f;
}

// ---------------------------------------------------------------------------
// Kernel A: smem-tiled pipelined query projection, f32x2 math, 256 blocks
// (2 resident per SM so one block's waits are covered by the other).
//   qpart[ks][b, d] = sum_{k in 256-slice ks} input[b,k] * Wq[d,k]
// grid (64 d-tiles of 16, KSPLIT=4) x 256 thr, 48 KB smem in 4 quarter-stages
// all cp.async'd up front. Warp computes 2 d's x 32 b (lane = b).
// ---------------------------------------------------------------------------
__global__ __launch_bounds__(256, 2) void qproj_kernel(
    const float* __restrict__ input, const float* __restrict__ Wq) {
  const int tid = threadIdx.x;
  const int warp = tid >> 5;
  const int lane = tid & 31;            // lane = b
  const int dt = blockIdx.x;            // d-tile (16 d's)
  const int ks = blockIdx.y;            // k-slice (256 k's)
  const int kbase = ks * (CC / KSPLIT);

  // quarter q at smq + q*768: [0,512) sIn (kc16 x b32), [512,768) sW (dl16 x kc16)
  extern __shared__ float4 smq[];

  // prologue: stage ALL four quarters, one commit group each
#pragma unroll
  for (int qq = 0; qq < 4; ++qq) {
    float4* sInQ = smq + qq * 768;
    float4* sWQ = sInQ + 512;
    const int kq = kbase + qq * 64;  // quarter covers k in [kq, kq+64)
#pragma unroll
    for (int i = 0; i < 2; ++i) {
      const int idx = i * 256 + tid;   // (b, kc), kc fast (16 per b)
      const int b = idx >> 4, kc = idx & 15;
      const float* src = input + (size_t)b * CC + kq + kc * 4;
      unsigned dst = (unsigned)__cvta_generic_to_shared(sInQ + kc * 32 + b);
      asm volatile("cp.async.cg.shared.global [%0], [%1], 16;" ::"r"(dst),
                   "l"(src));
    }
    {
      const int dl = tid >> 4, kc = tid & 15;  // 256 = 16 dl x 16 kc
      const float* src = Wq + (size_t)(dt * 16 + dl) * CC + kq + kc * 4;
      unsigned dst = (unsigned)__cvta_generic_to_shared(sWQ + dl * 16 + kc);
      asm volatile("cp.async.cg.shared.global [%0], [%1], 16;" ::"r"(dst),
                   "l"(src));
    }
    asm volatile("cp.async.commit_group;");
  }

  // accumulators: 2 d's, each 4 floats as 2 x f32x2
  u64 a0x = 0, a0y = 0, a1x = 0, a1y = 0;

#pragma unroll
  for (int qq = 0; qq < 4; ++qq) {
    if (qq == 0) asm volatile("cp.async.wait_group 3;");
    if (qq == 1) asm volatile("cp.async.wait_group 2;");
    if (qq == 2) asm volatile("cp.async.wait_group 1;");
    if (qq == 3) asm volatile("cp.async.wait_group 0;");
    __syncthreads();

    const float4* sInQ = smq + qq * 768;
    const float4* wrow = sInQ + 512 + warp * 2 * 16;

#pragma unroll
    for (int kc = 0; kc < 16; ++kc) {
      const ulonglong2 in2 = *(const ulonglong2*)(sInQ + kc * 32 + lane);
      const ulonglong2 w0 = *(const ulonglong2*)(wrow + kc);
      const ulonglong2 w1 = *(const ulonglong2*)(wrow + 16 + kc);
      ffma2(a0x, w0.x, in2.x); ffma2(a0y, w0.y, in2.y);
      ffma2(a1x, w1.x, in2.x); ffma2(a1y, w1.y, in2.y);
    }
  }

  const float2 f0a = u2f(a0x), f0b = u2f(a0y);
  const float2 f1a = u2f(a1x), f1b = u2f(a1y);
  float2 q;
  q.x = (f0a.x + f0a.y) + (f0b.x + f0b.y);
  q.y = (f1a.x + f1a.y) + (f1b.x + f1b.y);
  *(float2*)(&g_qpart[ks][lane * DH + dt * 16 + warp * 2]) = q;
}

// ---------------------------------------------------------------------------
// Kernel B: fused scores + online softmax + block merge + IN-KERNEL COMBINE.
// grid (NPART+1, BB): blocks 0..NPART-1 are producers (unchanged hot loop);
// block NPART per batch spin-waits on g_cnt[b] then combines the partials
// and writes both outputs (reads via __ldcg to bypass stale L1).
// Single wave guaranteed: 544 blocks <= 592 resident slots (48 KB smem).
// enc_h layout (D, T, B, H): keys[b,t,dir*H+h] = enc_h[((dir*T+t)*B+b)*H+h]
// ---------------------------------------------------------------------------
__global__ __launch_bounds__(128, 4) void attn_main_kernel(
    const float* __restrict__ enc_h, const float* __restrict__ bq,
    float* __restrict__ out) {
  const int b = blockIdx.y;
  const int warp = threadIdx.x >> 5;
  const int lane = threadIdx.x & 31;

  // ======================= consumer (combine) block =======================
  if (blockIdx.x == NPART) {
    const int j = threadIdx.x;
    if (j == 0) {
      while (*(volatile unsigned*)&g_cnt[b] < NPART) __nanosleep(64);
    }
    __syncthreads();
    __threadfence();
    if (j == 0) g_cnt[b] = 0;  // reset for next graph replay

    __shared__ float swv[NPART];
    __shared__ float s_inv;
    float M = -1e30f;
#pragma unroll
    for (int w = 0; w < NPART; ++w) M = fmaxf(M, __ldcg(&g_pm[b * NPART + w]));
    if (j < NPART) swv[j] = __expf(__ldcg(&g_pm[b * NPART + j]) - M);
    __syncthreads();
    if (j == 0) {
      float L = 0.f;
#pragma unroll
      for (int w = 0; w < NPART; ++w)
        L += __ldcg(&g_pl[b * NPART + w]) * swv[w];
      s_inv = 1.f / L;
    }
    __syncthreads();
    const float invL = s_inv;

    // attn_values: 1024 d = 256 float4 over 128 threads (2 each)
    const float4* pab = (const float4*)(g_pa + (size_t)b * NPART * DH);
#pragma unroll
    for (int g = 0; g < 2; ++g) {
      const int c4 = g * 128 + j;  // float4 column 0..255
      float4 v = make_float4(0.f, 0.f, 0.f, 0.f);
#pragma unroll
      for (int w = 0; w < NPART; ++w) {
        const float4 p = __ldcg(pab + (size_t)w * 256 + c4);
        const float sw_ = swv[w];
        v.x += sw_ * p.x; v.y += sw_ * p.y;
        v.z += sw_ * p.z; v.w += sw_ * p.w;
      }
      v.x *= invL; v.y *= invL; v.z *= invL; v.w *= invL;
      ((float4*)(out + b * DH))[c4] = v;
    }

    // normalized scores: 2048 floats = 512 float4 over 128 threads (4 each)
    const float4* sc4 = (const float4*)(g_scores + b * TT);
    float4* out4 = (float4*)(out + BB * DH + b * TT);
#pragma unroll
    for (int g = 0; g < 4; ++g) {
      const int idx = g * 128 + j;
      const float4 s4 = __ldcg(sc4 + idx);
      float4 o;
      o.x = __expf(s4.x - M) * invL;
      o.y = __expf(s4.y - M) * invL;
      o.z = __expf(s4.z - M) * invL;
      o.w = __expf(s4.w - M) * invL;
      out4[idx] = o;
    }
    return;
  }

  // ========================== producer blocks ============================
  const int widx = blockIdx.x * 4 + warp;   // 0..NWARP-1 within this batch
  const int t0 = widx * WT;

  const float scale = 0.04419417382415922f;  // 1/sqrt(512)

  extern __shared__ float4 ring[];           // [4 warps][SSTAGES][256] = 48KB
  float4* ringw = ring + warp * (SSTAGES * 256);

  const size_t tstride = (size_t)BB * HH;          // floats per timestep
  const size_t dirstride = (size_t)TT * BB * HH;   // floats per direction
  const float* base0 = enc_h + ((size_t)t0 * BB + b) * HH + lane * 4;
  const float* base1 = base0 + dirstride;

#define LOAD_STAGE(T, SLOT)                                                  \
  {                                                                          \
    const float* r0_ = base0 + (size_t)(T)*tstride;                          \
    const float* r1_ = base1 + (size_t)(T)*tstride;                          \
    float4* d_ = ringw + (SLOT)*256 + lane;                                  \
    _Pragma("unroll") for (int p = 0; p < 4; ++p) {                          \
      unsigned sa_ = (unsigned)__cvta_generic_to_shared(d_ + p * 32);        \
      asm volatile("cp.async.cg.shared.global [%0], [%1], 16;" ::"r"(sa_),   \
                   "l"(r0_ + p * 128));                                      \
    }                                                                        \
    _Pragma("unroll") for (int p = 0; p < 4; ++p) {                          \
      unsigned sa_ = (unsigned)__cvta_generic_to_shared(d_ + 128 + p * 32);  \
      asm volatile("cp.async.cg.shared.global [%0], [%1], 16;" ::"r"(sa_),   \
                   "l"(r1_ + p * 128));                                      \
    }                                                                        \
    asm volatile("cp.async.commit_group;");                                  \
  }

  // prologue FIRST: stages 0..PRE-1 in flight before any q work
  LOAD_STAGE(0, 0)
  LOAD_STAGE(1, 1)

  // q for this lane: q[p] covers d = p*128 + lane*4 (hidden under stage 0)
  float4 q[8];
#pragma unroll
  for (int p = 0; p < 8; ++p) {
    const int d = p * 128 + lane * 4;
    const float4 bb = *(const float4*)(bq + d);
    float4 acc = bb;
#pragma unroll
    for (int ks = 0; ks < KSPLIT; ++ks) {
      const float4 pp = *(const float4*)(&g_qpart[ks][b * DH + d]);
      acc.x += pp.x; acc.y += pp.y; acc.z += pp.z; acc.w += pp.w;
    }
    q[p] = acc;
  }

  float4 a[8];
#pragma unroll
  for (int p = 0; p < 8; ++p) a[p] = make_float4(0.f, 0.f, 0.f, 0.f);
  float m = -1e30f, l = 0.f;

#pragma unroll
  for (int i = 0; i < WT; ++i) {
    // exact-count waits: only real groups are committed
    if (i + PRE < WT) {
      LOAD_STAGE(i + PRE, (i + PRE) % SSTAGES)
      asm volatile("cp.async.wait_group 2;");   // stage i complete
    } else if (i == WT - 2) {
      asm volatile("cp.async.wait_group 1;");   // one group (stage WT-1) left
    } else {                                    // i == WT-1
      asm volatile("cp.async.wait_group 0;");
    }

    const float4* kp = ringw + (i % SSTAGES) * 256 + lane;
    float4 k[8];
#pragma unroll
    for (int p = 0; p < 8; ++p) k[p] = kp[p * 32];

    float s = 0.f;
#pragma unroll
    for (int p = 0; p < 8; ++p)
      s += q[p].x * k[p].x + q[p].y * k[p].y + q[p].z * k[p].z +
           q[p].w * k[p].w;
#pragma unroll
    for (int off = 16; off >= 1; off >>= 1)
      s += __shfl_xor_sync(0xffffffffu, s, off);
    s *= scale;

    if (lane == 0) g_scores[b * TT + t0 + i] = s;

    if (s > m) {  // warp-uniform branch (s identical on all lanes)
      const float r = __expf(m - s);
#pragma unroll
      for (int p = 0; p < 8; ++p) {
        a[p].x *= r; a[p].y *= r; a[p].z *= r; a[p].w *= r;
      }
      l *= r;
      m = s;
    }
    const float w = __expf(s - m);
    l += w;
#pragma unroll
    for (int p = 0; p < 8; ++p) {
      a[p].x += w * k[p].x;
      a[p].y += w * k[p].y;
      a[p].z += w * k[p].z;
      a[p].w += w * k[p].w;
    }
  }
#undef LOAD_STAGE

  // ---- block-level merge of the 4 warps' partials (reuse ring smem) ----
  __shared__ float s_m[4], s_l[4];
  if (lane == 0) { s_m[warp] = m; s_l[warp] = l; }
  __syncthreads();

  const float Mb = fmaxf(fmaxf(s_m[0], s_m[1]), fmaxf(s_m[2], s_m[3]));
  const float Lb = s_l[0] * __expf(s_m[0] - Mb) + s_l[1] * __expf(s_m[1] - Mb) +
                   s_l[2] * __expf(s_m[2] - Mb) + s_l[3] * __expf(s_m[3] - Mb);
  const float wf = __expf(m - Mb);  // warp-uniform rescale factor

  // scaled a -> smem: ring[warp*256 + p*32 + lane] covers d = p*128+lane*4
  float4* mw = ring + warp * 256;
#pragma unroll
  for (int p = 0; p < 8; ++p) {
    float4 v = a[p];
    v.x *= wf; v.y *= wf; v.z *= wf; v.w *= wf;
    mw[p * 32 + lane] = v;
  }
  __syncthreads();

  // cooperative sum of 4 warps' vectors -> one partial per block
  float4* pa4 = (float4*)(g_pa + (size_t)(b * NPART + blockIdx.x) * DH);
#pragma unroll
  for (int r = 0; r < 2; ++r) {
    const int idx = r * 128 + threadIdx.x;  // 0..255 float4s
    const float4 v0 = ring[idx];
    const float4 v1 = ring[256 + idx];
    const float4 v2 = ring[512 + idx];
    const float4 v3 = ring[768 + idx];
    float4 v;
    v.x = v0.x + v1.x + v2.x + v3.x;
    v.y = v0.y + v1.y + v2.y + v3.y;
    v.z = v0.z + v1.z + v2.z + v3.z;
    v.w = v0.w + v1.w + v2.w + v3.w;
    pa4[idx] = v;
  }
  if (threadIdx.x == 0) {
    g_pm[b * NPART + blockIdx.x] = Mb;
    g_pl[b * NPART + blockIdx.x] = Lb;
  }

  // publish: all writes visible, then bump the batch counter
  __threadfence();
  __syncthreads();
  if (threadIdx.x == 0) atomicAdd(&g_cnt[b], 1u);
}

// ---------------------------------------------------------------------------
extern "C" void kernel_launch(void* const* d_in, const int* in_sizes, int n_in,
                              void* d_out, int out_size) {
  const float* input = (const float*)d_in[0];   // (32, 1024)
  const float* enc_h = (const float*)d_in[1];   // (2, 2048, 32, 512)
  // d_in[2] decoder_state: unused
  const float* Wq = (const float*)d_in[3];      // (1024, 1024)
  const float* bq = (const float*)d_in[4];      // (1024,)
  // d_in[5] t: unused
  float* out = (float*)d_out;  // [attn_values (32*1024)] ++ [attn_scores (32*2048)]

  const int smem_main = 4 * SSTAGES * 256 * sizeof(float4);  // 48 KB
  const int smem_qp = 3072 * sizeof(float4);                 // 48 KB
  cudaFuncSetAttribute(attn_main_kernel,
                       cudaFuncAttributeMaxDynamicSharedMemorySize, smem_main);
  cudaFuncSetAttribute(qproj_kernel,
                       cudaFuncAttributeMaxDynamicSharedMemorySize, smem_qp);

  qproj_kernel<<<dim3(64, KSPLIT), 256, smem_qp>>>(input, Wq);
  attn_main_kernel<<<dim3(NPART + 1, BB), 128, smem_main>>>(enc_h, bq, out);
}

// round 13
// speedup vs baseline: 1.0893x; 1.0893x over previous
#include <cuda_runtime.h>
#include <cuda_bf16.h>

// Problem constants (fixed by setup_inputs)
#define BB 32      // batch
#define TT 2048    // timesteps
#define HH 512     // hidden per direction
#define DH 1024    // D*H
#define CC 1024    // input feature size
#define NWARP 64   // fused-pass warps per batch
#define WT (TT / NWARP)  // 32 timesteps per warp
#define NPART 16   // merged partials per batch (one per block)
#define SSTAGES 3  // smem ring stages per warp (1 timestep = 4KB each)
#define PRE 2      // stages kept in flight
#define KSPLIT 4   // qproj K-split (k-slice of 256 per block)

typedef unsigned long long u64;

// ---------------- scratch (no runtime allocation allowed) ----------------
__device__ float g_qpart[KSPLIT][BB * DH];         // split-K query partials
__device__ float g_scores[BB * TT];                // raw (pre-softmax) scores
__device__ float g_pm[BB * NPART];                 // per-block running max
__device__ float g_pl[BB * NPART];                 // per-block running sum
__device__ float g_pa[(size_t)BB * NPART * DH];    // per-block weighted accum (2 MB)

// packed f32x2 fma helpers (Blackwell FFMA2 — PTX-only)
__device__ __forceinline__ void ffma2(u64& d, u64 a, u64 b) {
  asm("fma.rn.f32x2 %0, %1, %2, %0;" : "+l"(d) : "l"(a), "l"(b));
}
__device__ __forceinline__ float2 u2f(u64 v) {
  float2 f;
  asm("mov.b64 {%0, %1}, %2;" : "=f"(f.x), "=f"(f.y) : "l"(v));
  return f;
}
// PDL: block until the upstream grid in the same stream has completed.
// No-op if no dependency was configured (fallback launches stay correct).
__device__ __forceinline__ void grid_dep_wait() {
  asm volatile("griddepcontrol.wait;" ::: "memory");
}

// ---------------------------------------------------------------------------
// Kernel A: smem-tiled pipelined query projection, f32x2 math, 256 blocks.
//   qpart[ks][b, d] = sum_{k in 256-slice ks} input[b,k] * Wq[d,k]
// grid (64 d-tiles of 16, KSPLIT=4) x 256 thr, 48 KB smem in 4 quarter-stages
// all cp.async'd up front. Warp computes 2 d's x 32 b (lane = b).
// ---------------------------------------------------------------------------
__global__ __launch_bounds__(256, 2) void qproj_kernel(
    const float* __restrict__ input, const float* __restrict__ Wq) {
  const int tid = threadIdx.x;
  const int warp = tid >> 5;
  const int lane = tid & 31;            // lane = b
  const int dt = blockIdx.x;            // d-tile (16 d's)
  const int ks = blockIdx.y;            // k-slice (256 k's)
  const int kbase = ks * (CC / KSPLIT);

  // quarter q at smq + q*768: [0,512) sIn (kc16 x b32), [512,768) sW (dl16 x kc16)
  extern __shared__ float4 smq[];

  // prologue: stage ALL four quarters, one commit group each
#pragma unroll
  for (int qq = 0; qq < 4; ++qq) {
    float4* sInQ = smq + qq * 768;
    float4* sWQ = sInQ + 512;
    const int kq = kbase + qq * 64;  // quarter covers k in [kq, kq+64)
#pragma unroll
    for (int i = 0; i < 2; ++i) {
      const int idx = i * 256 + tid;   // (b, kc), kc fast (16 per b)
      const int b = idx >> 4, kc = idx & 15;
      const float* src = input + (size_t)b * CC + kq + kc * 4;
      unsigned dst = (unsigned)__cvta_generic_to_shared(sInQ + kc * 32 + b);
      asm volatile("cp.async.cg.shared.global [%0], [%1], 16;" ::"r"(dst),
                   "l"(src));
    }
    {
      const int dl = tid >> 4, kc = tid & 15;  // 256 = 16 dl x 16 kc
      const float* src = Wq + (size_t)(dt * 16 + dl) * CC + kq + kc * 4;
      unsigned dst = (unsigned)__cvta_generic_to_shared(sWQ + dl * 16 + kc);
      asm volatile("cp.async.cg.shared.global [%0], [%1], 16;" ::"r"(dst),
                   "l"(src));
    }
    asm volatile("cp.async.commit_group;");
  }

  // accumulators: 2 d's, each 4 floats as 2 x f32x2
  u64 a0x = 0, a0y = 0, a1x = 0, a1y = 0;

#pragma unroll
  for (int qq = 0; qq < 4; ++qq) {
    if (qq == 0) asm volatile("cp.async.wait_group 3;");
    if (qq == 1) asm volatile("cp.async.wait_group 2;");
    if (qq == 2) asm volatile("cp.async.wait_group 1;");
    if (qq == 3) asm volatile("cp.async.wait_group 0;");
    __syncthreads();

    const float4* sInQ = smq + qq * 768;
    const float4* wrow = sInQ + 512 + warp * 2 * 16;

#pragma unroll
    for (int kc = 0; kc < 16; ++kc) {
      const ulonglong2 in2 = *(const ulonglong2*)(sInQ + kc * 32 + lane);
      const ulonglong2 w0 = *(const ulonglong2*)(wrow + kc);
      const ulonglong2 w1 = *(const ulonglong2*)(wrow + 16 + kc);
      ffma2(a0x, w0.x, in2.x); ffma2(a0y, w0.y, in2.y);
      ffma2(a1x, w1.x, in2.x); ffma2(a1y, w1.y, in2.y);
    }
  }

  const float2 f0a = u2f(a0x), f0b = u2f(a0y);
  const float2 f1a = u2f(a1x), f1b = u2f(a1y);
  float2 q;
  q.x = (f0a.x + f0a.y) + (f0b.x + f0b.y);
  q.y = (f1a.x + f1a.y) + (f1b.x + f1b.y);
  *(float2*)(&g_qpart[ks][lane * DH + dt * 16 + warp * 2]) = q;
}

// ---------------------------------------------------------------------------
// Kernel B: warp-autonomous fused scores + online softmax, cp.async pipeline,
// block-level partial merge. PDL: launches while qproj runs, issues its key
// prologue, then griddepcontrol.wait before consuming g_qpart.
// grid (NWARP/4=16, BB)=512 blocks, 48 KB smem -> single wave.
// enc_h layout (D, T, B, H): keys[b,t,dir*H+h] = enc_h[((dir*T+t)*B+b)*H+h]
// ---------------------------------------------------------------------------
__global__ __launch_bounds__(128, 4) void attn_main_kernel(
    const float* __restrict__ enc_h, const float* __restrict__ bq) {
  const int b = blockIdx.y;
  const int warp = threadIdx.x >> 5;
  const int lane = threadIdx.x & 31;
  const int widx = blockIdx.x * 4 + warp;   // 0..NWARP-1 within this batch
  const int t0 = widx * WT;

  const float scale = 0.04419417382415922f;  // 1/sqrt(512)

  extern __shared__ float4 ring[];           // [4 warps][SSTAGES][256] = 48KB
  float4* ringw = ring + warp * (SSTAGES * 256);

  const size_t tstride = (size_t)BB * HH;          // floats per timestep
  const size_t dirstride = (size_t)TT * BB * HH;   // floats per direction
  const float* base0 = enc_h + ((size_t)t0 * BB + b) * HH + lane * 4;
  const float* base1 = base0 + dirstride;

#define LOAD_STAGE(T, SLOT)                                                  \
  {                                                                          \
    const float* r0_ = base0 + (size_t)(T)*tstride;                          \
    const float* r1_ = base1 + (size_t)(T)*tstride;                          \
    float4* d_ = ringw + (SLOT)*256 + lane;                                  \
    _Pragma("unroll") for (int p = 0; p < 4; ++p) {                          \
      unsigned sa_ = (unsigned)__cvta_generic_to_shared(d_ + p * 32);        \
      asm volatile("cp.async.cg.shared.global [%0], [%1], 16;" ::"r"(sa_),   \
                   "l"(r0_ + p * 128));                                      \
    }                                                                        \
    _Pragma("unroll") for (int p = 0; p < 4; ++p) {                          \
      unsigned sa_ = (unsigned)__cvta_generic_to_shared(d_ + 128 + p * 32);  \
      asm volatile("cp.async.cg.shared.global [%0], [%1], 16;" ::"r"(sa_),   \
                   "l"(r1_ + p * 128));                                      \
    }                                                                        \
    asm volatile("cp.async.commit_group;");                                  \
  }

  // prologue FIRST: independent of qproj — overlaps it under PDL
  LOAD_STAGE(0, 0)
  LOAD_STAGE(1, 1)

  // wait for qproj grid completion before consuming its output
  grid_dep_wait();

  // q for this lane: q[p] covers d = p*128 + lane*4
  float4 q[8];
#pragma unroll
  for (int p = 0; p < 8; ++p) {
    const int d = p * 128 + lane * 4;
    const float4 bb = *(const float4*)(bq + d);
    float4 acc = bb;
#pragma unroll
    for (int ks = 0; ks < KSPLIT; ++ks) {
      const float4 pp = *(const float4*)(&g_qpart[ks][b * DH + d]);
      acc.x += pp.x; acc.y += pp.y; acc.z += pp.z; acc.w += pp.w;
    }
    q[p] = acc;
  }

  float4 a[8];
#pragma unroll
  for (int p = 0; p < 8; ++p) a[p] = make_float4(0.f, 0.f, 0.f, 0.f);
  float m = -1e30f, l = 0.f;

#pragma unroll
  for (int i = 0; i < WT; ++i) {
    // exact-count waits: only real groups are committed
    if (i + PRE < WT) {
      LOAD_STAGE(i + PRE, (i + PRE) % SSTAGES)
      asm volatile("cp.async.wait_group 2;");   // stage i complete
    } else if (i == WT - 2) {
      asm volatile("cp.async.wait_group 1;");   // one group (stage WT-1) left
    } else {                                    // i == WT-1
      asm volatile("cp.async.wait_group 0;");
    }

    const float4* kp = ringw + (i % SSTAGES) * 256 + lane;
    float4 k[8];
#pragma unroll
    for (int p = 0; p < 8; ++p) k[p] = kp[p * 32];

    float s = 0.f;
#pragma unroll
    for (int p = 0; p < 8; ++p)
      s += q[p].x * k[p].x + q[p].y * k[p].y + q[p].z * k[p].z +
           q[p].w * k[p].w;
#pragma unroll
    for (int off = 16; off >= 1; off >>= 1)
      s += __shfl_xor_sync(0xffffffffu, s, off);
    s *= scale;

    if (lane == 0) g_scores[b * TT + t0 + i] = s;

    if (s > m) {  // warp-uniform branch (s identical on all lanes)
      const float r = __expf(m - s);
#pragma unroll
      for (int p = 0; p < 8; ++p) {
        a[p].x *= r; a[p].y *= r; a[p].z *= r; a[p].w *= r;
      }
      l *= r;
      m = s;
    }
    const float w = __expf(s - m);
    l += w;
#pragma unroll
    for (int p = 0; p < 8; ++p) {
      a[p].x += w * k[p].x;
      a[p].y += w * k[p].y;
      a[p].z += w * k[p].z;
      a[p].w += w * k[p].w;
    }
  }
#undef LOAD_STAGE

  // ---- block-level merge of the 4 warps' partials (reuse ring smem) ----
  __shared__ float s_m[4], s_l[4];
  if (lane == 0) { s_m[warp] = m; s_l[warp] = l; }
  __syncthreads();

  const float Mb = fmaxf(fmaxf(s_m[0], s_m[1]), fmaxf(s_m[2], s_m[3]));
  const float Lb = s_l[0] * __expf(s_m[0] - Mb) + s_l[1] * __expf(s_m[1] - Mb) +
                   s_l[2] * __expf(s_m[2] - Mb) + s_l[3] * __expf(s_m[3] - Mb);
  const float wf = __expf(m - Mb);  // warp-uniform rescale factor

  // scaled a -> smem: ring[warp*256 + p*32 + lane] covers d = p*128+lane*4
  float4* mw = ring + warp * 256;
#pragma unroll
  for (int p = 0; p < 8; ++p) {
    float4 v = a[p];
    v.x *= wf; v.y *= wf; v.z *= wf; v.w *= wf;
    mw[p * 32 + lane] = v;
  }
  __syncthreads();

  // cooperative sum of 4 warps' vectors -> one partial per block
  float4* pa4 = (float4*)(g_pa + (size_t)(b * NPART + blockIdx.x) * DH);
#pragma unroll
  for (int r = 0; r < 2; ++r) {
    const int idx = r * 128 + threadIdx.x;  // 0..255 float4s
    const float4 v0 = ring[idx];
    const float4 v1 = ring[256 + idx];
    const float4 v2 = ring[512 + idx];
    const float4 v3 = ring[768 + idx];
    float4 v;
    v.x = v0.x + v1.x + v2.x + v3.x;
    v.y = v0.y + v1.y + v2.y + v3.y;
    v.z = v0.z + v1.z + v2.z + v3.z;
    v.w = v0.w + v1.w + v2.w + v3.w;
    pa4[idx] = v;
  }
  if (threadIdx.x == 0) {
    g_pm[b * NPART + blockIdx.x] = Mb;
    g_pl[b * NPART + blockIdx.x] = Lb;
  }
}

// ---------------------------------------------------------------------------
// Kernel C: combine per-block partials -> attn_values + normalized scores.
// PDL: launches during attn_main, waits at entry (ramp overlapped).
// grid (BB, 8), 128 threads: block handles 128 d's + 256 score elements.
// ---------------------------------------------------------------------------
__global__ __launch_bounds__(128) void combine_kernel(float* __restrict__ out) {
  grid_dep_wait();   // attn_main grid complete; its writes visible

  const int b = blockIdx.x;
  const int ds = blockIdx.y;
  const int j = threadIdx.x;

  __shared__ float sm[NPART], sw[NPART];
  __shared__ float sL;
  if (j < NPART) sm[j] = g_pm[b * NPART + j];
  __syncthreads();

  float M = -1e30f;
#pragma unroll
  for (int w = 0; w < NPART; ++w) M = fmaxf(M, sm[w]);
  if (j < NPART) sw[j] = __expf(sm[j] - M);
  __syncthreads();

  if (j == 0) {
    float L = 0.f;
#pragma unroll
    for (int w = 0; w < NPART; ++w) L += g_pl[b * NPART + w] * sw[w];
    sL = 1.f / L;
  }
  __syncthreads();
  const float invL = sL;

  const int d = ds * 128 + j;
  const float* pa = g_pa + (size_t)b * NPART * DH + d;
  float v0 = 0.f, v1 = 0.f, v2 = 0.f, v3 = 0.f;
#pragma unroll
  for (int w = 0; w < NPART; w += 4) {
    v0 += sw[w + 0] * pa[(size_t)(w + 0) * DH];
    v1 += sw[w + 1] * pa[(size_t)(w + 1) * DH];
    v2 += sw[w + 2] * pa[(size_t)(w + 2) * DH];
    v3 += sw[w + 3] * pa[(size_t)(w + 3) * DH];
  }
  out[b * DH + d] = (v0 + v1 + v2 + v3) * invL;

  // fused scores normalization: this block covers t in [ds*256, ds*256+256)
  const int tb = ds * 256 + j * 2;
  const float2 s2 = *(const float2*)(g_scores + b * TT + tb);
  float2 o2;
  o2.x = __expf(s2.x - M) * invL;
  o2.y = __expf(s2.y - M) * invL;
  *(float2*)(out + BB * DH + b * TT + tb) = o2;
}

// ---------------------------------------------------------------------------
extern "C" void kernel_launch(void* const* d_in, const int* in_sizes, int n_in,
                              void* d_out, int out_size) {
  const float* input = (const float*)d_in[0];   // (32, 1024)
  const float* enc_h = (const float*)d_in[1];   // (2, 2048, 32, 512)
  // d_in[2] decoder_state: unused
  const float* Wq = (const float*)d_in[3];      // (1024, 1024)
  const float* bq = (const float*)d_in[4];      // (1024,)
  // d_in[5] t: unused
  float* out = (float*)d_out;  // [attn_values (32*1024)] ++ [attn_scores (32*2048)]

  const int smem_main = 4 * SSTAGES * 256 * sizeof(float4);  // 48 KB
  const int smem_qp = 3072 * sizeof(float4);                 // 48 KB
  cudaFuncSetAttribute(attn_main_kernel,
                       cudaFuncAttributeMaxDynamicSharedMemorySize, smem_main);
  cudaFuncSetAttribute(qproj_kernel,
                       cudaFuncAttributeMaxDynamicSharedMemorySize, smem_qp);

  qproj_kernel<<<dim3(64, KSPLIT), 256, smem_qp>>>(input, Wq);

  // attn_main with PDL (falls back to a plain launch on error)
  {
    cudaLaunchConfig_t cfg = {};
    cfg.gridDim = dim3(NWARP / 4, BB);
    cfg.blockDim = dim3(128, 1, 1);
    cfg.dynamicSmemBytes = smem_main;
    cfg.stream = 0;
    cudaLaunchAttribute at[1];
    at[0].id = cudaLaunchAttributeProgrammaticStreamSerialization;
    at[0].val.programmaticStreamSerializationAllowed = 1;
    cfg.attrs = at;
    cfg.numAttrs = 1;
    if (cudaLaunchKernelEx(&cfg, attn_main_kernel, enc_h, bq) != cudaSuccess)
      attn_main_kernel<<<dim3(NWARP / 4, BB), 128, smem_main>>>(enc_h, bq);
  }

  // combine with PDL (falls back to a plain launch on error)
  {
    cudaLaunchConfig_t cfg = {};
    cfg.gridDim = dim3(BB, 8);
    cfg.blockDim = dim3(128, 1, 1);
    cfg.dynamicSmemBytes = 0;
    cfg.stream = 0;
    cudaLaunchAttribute at[1];
    at[0].id = cudaLaunchAttributeProgrammaticStreamSerialization;
    at[0].val.programmaticStreamSerializationAllowed = 1;
    cfg.attrs = at;
    cfg.numAttrs = 1;
    if (cudaLaunchKernelEx(&cfg, combine_kernel, out) != cudaSuccess)
      combine_kernel<<<dim3(BB, 8), 128>>>(out);
  }
}

// round 14
// speedup vs baseline: 1.1474x; 1.0533x over previous
#include <cuda_runtime.h>
#include <cuda_bf16.h>

// Problem constants (fixed by setup_inputs)
#define BB 32      // batch
#define TT 2048    // timesteps
#define HH 512     // hidden per direction
#define DH 1024    // D*H
#define CC 1024    // input feature size
#define NWARP 64   // fused-pass warps per batch
#define WT (TT / NWARP)  // 32 timesteps per warp
#define NPART 16   // merged partials per batch (one per block)
#define SSTAGES 3  // smem ring stages per warp (1 timestep = 4KB each)
#define PRE 2      // stages kept in flight
#define KSPLIT 4   // qproj K-split (k-slice of 256 per block)

typedef unsigned long long u64;

// ---------------- scratch (no runtime allocation allowed) ----------------
__device__ float g_qpart[KSPLIT][BB * DH];         // split-K query partials
__device__ float g_scores[BB * TT];                // raw (pre-softmax) scores
__device__ float g_pm[BB * NPART];                 // per-block running max
__device__ float g_pl[BB * NPART];                 // per-block running sum
__device__ float g_pa[(size_t)BB * NPART * DH];    // per-block weighted accum (2 MB)

// packed f32x2 fma helpers (Blackwell FFMA2 — PTX-only)
__device__ __forceinline__ void ffma2(u64& d, u64 a, u64 b) {
  asm("fma.rn.f32x2 %0, %1, %2, %0;" : "+l"(d) : "l"(a), "l"(b));
}
__device__ __forceinline__ float2 u2f(u64 v) {
  float2 f;
  asm("mov.b64 {%0, %1}, %2;" : "=f"(f.x), "=f"(f.y) : "l"(v));
  return f;
}
// PDL: block until the upstream grid in the same stream has completed.
// No-op if no dependency was configured (fallback launches stay correct).
__device__ __forceinline__ void grid_dep_wait() {
  asm volatile("griddepcontrol.wait;" ::: "memory");
}

// ---------------------------------------------------------------------------
// Kernel A (best measured: 9.8us): smem-tiled, internally pipelined query
// projection with f32x2 math.
//   qpart[ks][b, d] = sum_{k in 256-slice ks} input[b,k] * Wq[d,k]
// grid (32 d-tiles, KSPLIT=4) x 256 thr, 64 KB smem in 4 quarter-stages,
// all quarters cp.async'd up front; compute of quarter q overlaps arrival
// of q+1..3. Warp computes 4 d's x 32 b (lane = b).
// ---------------------------------------------------------------------------
__global__ __launch_bounds__(256, 2) void qproj_kernel(
    const float* __restrict__ input, const float* __restrict__ Wq) {
  const int tid = threadIdx.x;
  const int warp = tid >> 5;
  const int lane = tid & 31;            // lane = b
  const int dt = blockIdx.x;            // d-tile (32 d's)
  const int ks = blockIdx.y;            // k-slice (256 k's)
  const int kbase = ks * (CC / KSPLIT);

  // smem: quarter q at smq + q*1024: [0,512) sIn (kc16 x b32), [512,1024) sW
  extern __shared__ float4 smq[];

  // prologue: stage ALL four quarters, one commit group each
#pragma unroll
  for (int qq = 0; qq < 4; ++qq) {
    float4* sInQ = smq + qq * 1024;
    float4* sWQ = sInQ + 512;
    const int kq = kbase + qq * 64;  // quarter covers k in [kq, kq+64)
#pragma unroll
    for (int i = 0; i < 2; ++i) {
      const int idx = i * 256 + tid;   // (b, kc), kc fast (16 per b)
      const int b = idx >> 4, kc = idx & 15;
      const float* src = input + (size_t)b * CC + kq + kc * 4;
      unsigned dst = (unsigned)__cvta_generic_to_shared(sInQ + kc * 32 + b);
      asm volatile("cp.async.cg.shared.global [%0], [%1], 16;" ::"r"(dst),
                   "l"(src));
    }
#pragma unroll
    for (int i = 0; i < 2; ++i) {
      const int idx = i * 256 + tid;   // (dl, kc), kc fast (16 per dl)
      const int dl = idx >> 4, kc = idx & 15;
      const float* src = Wq + (size_t)(dt * 32 + dl) * CC + kq + kc * 4;
      unsigned dst = (unsigned)__cvta_generic_to_shared(sWQ + dl * 16 + kc);
      asm volatile("cp.async.cg.shared.global [%0], [%1], 16;" ::"r"(dst),
                   "l"(src));
    }
    asm volatile("cp.async.commit_group;");
  }

  // accumulators: 4 d's, each 4 floats as 2 x f32x2
  u64 a0x = 0, a0y = 0, a1x = 0, a1y = 0;
  u64 a2x = 0, a2y = 0, a3x = 0, a3y = 0;

#pragma unroll
  for (int qq = 0; qq < 4; ++qq) {
    if (qq == 0) asm volatile("cp.async.wait_group 3;");
    if (qq == 1) asm volatile("cp.async.wait_group 2;");
    if (qq == 2) asm volatile("cp.async.wait_group 1;");
    if (qq == 3) asm volatile("cp.async.wait_group 0;");
    __syncthreads();

    const float4* sInQ = smq + qq * 1024;
    const float4* wrow = sInQ + 512 + warp * 4 * 16;

#pragma unroll
    for (int kc = 0; kc < 16; ++kc) {
      const ulonglong2 in2 = *(const ulonglong2*)(sInQ + kc * 32 + lane);
      const ulonglong2 w0 = *(const ulonglong2*)(wrow + kc);
      const ulonglong2 w1 = *(const ulonglong2*)(wrow + 16 + kc);
      const ulonglong2 w2 = *(const ulonglong2*)(wrow + 32 + kc);
      const ulonglong2 w3 = *(const ulonglong2*)(wrow + 48 + kc);
      ffma2(a0x, w0.x, in2.x); ffma2(a0y, w0.y, in2.y);
      ffma2(a1x, w1.x, in2.x); ffma2(a1y, w1.y, in2.y);
      ffma2(a2x, w2.x, in2.x); ffma2(a2y, w2.y, in2.y);
      ffma2(a3x, w3.x, in2.x); ffma2(a3y, w3.y, in2.y);
    }
  }

  const float2 f0a = u2f(a0x), f0b = u2f(a0y);
  const float2 f1a = u2f(a1x), f1b = u2f(a1y);
  const float2 f2a = u2f(a2x), f2b = u2f(a2y);
  const float2 f3a = u2f(a3x), f3b = u2f(a3y);
  float4 q;
  q.x = (f0a.x + f0a.y) + (f0b.x + f0b.y);
  q.y = (f1a.x + f1a.y) + (f1b.x + f1b.y);
  q.z = (f2a.x + f2a.y) + (f2b.x + f2b.y);
  q.w = (f3a.x + f3a.y) + (f3b.x + f3b.y);
  *(float4*)(&g_qpart[ks][lane * DH + dt * 32 + warp * 4]) = q;
}

// ---------------------------------------------------------------------------
// Kernel B: warp-autonomous fused scores + online softmax, cp.async pipeline,
// block-level partial merge. PDL: launches while qproj runs, issues its key
// prologue, then griddepcontrol.wait before consuming g_qpart.
// grid (NWARP/4=16, BB)=512 blocks, 48 KB smem -> single wave.
// enc_h layout (D, T, B, H): keys[b,t,dir*H+h] = enc_h[((dir*T+t)*B+b)*H+h]
// ---------------------------------------------------------------------------
__global__ __launch_bounds__(128, 4) void attn_main_kernel(
    const float* __restrict__ enc_h, const float* __restrict__ bq) {
  const int b = blockIdx.y;
  const int warp = threadIdx.x >> 5;
  const int lane = threadIdx.x & 31;
  const int widx = blockIdx.x * 4 + warp;   // 0..NWARP-1 within this batch
  const int t0 = widx * WT;

  const float scale = 0.04419417382415922f;  // 1/sqrt(512)

  extern __shared__ float4 ring[];           // [4 warps][SSTAGES][256] = 48KB
  float4* ringw = ring + warp * (SSTAGES * 256);

  const size_t tstride = (size_t)BB * HH;          // floats per timestep
  const size_t dirstride = (size_t)TT * BB * HH;   // floats per direction
  const float* base0 = enc_h + ((size_t)t0 * BB + b) * HH + lane * 4;
  const float* base1 = base0 + dirstride;

#define LOAD_STAGE(T, SLOT)                                                  \
  {                                                                          \
    const float* r0_ = base0 + (size_t)(T)*tstride;                          \
    const float* r1_ = base1 + (size_t)(T)*tstride;                          \
    float4* d_ = ringw + (SLOT)*256 + lane;                                  \
    _Pragma("unroll") for (int p = 0; p < 4; ++p) {                          \
      unsigned sa_ = (unsigned)__cvta_generic_to_shared(d_ + p * 32);        \
      asm volatile("cp.async.cg.shared.global [%0], [%1], 16;" ::"r"(sa_),   \
                   "l"(r0_ + p * 128));                                      \
    }                                                                        \
    _Pragma("unroll") for (int p = 0; p < 4; ++p) {                          \
      unsigned sa_ = (unsigned)__cvta_generic_to_shared(d_ + 128 + p * 32);  \
      asm volatile("cp.async.cg.shared.global [%0], [%1], 16;" ::"r"(sa_),   \
                   "l"(r1_ + p * 128));                                      \
    }                                                                        \
    asm volatile("cp.async.commit_group;");                                  \
  }

  // prologue FIRST: independent of qproj — overlaps it under PDL
  LOAD_STAGE(0, 0)
  LOAD_STAGE(1, 1)

  // wait for qproj grid completion before consuming its output
  grid_dep_wait();

  // q for this lane: q[p] covers d = p*128 + lane*4
  float4 q[8];
#pragma unroll
  for (int p = 0; p < 8; ++p) {
    const int d = p * 128 + lane * 4;
    const float4 bb = *(const float4*)(bq + d);
    float4 acc = bb;
#pragma unroll
    for (int ks = 0; ks < KSPLIT; ++ks) {
      const float4 pp = *(const float4*)(&g_qpart[ks][b * DH + d]);
      acc.x += pp.x; acc.y += pp.y; acc.z += pp.z; acc.w += pp.w;
    }
    q[p] = acc;
  }

  float4 a[8];
#pragma unroll
  for (int p = 0; p < 8; ++p) a[p] = make_float4(0.f, 0.f, 0.f, 0.f);
  float m = -1e30f, l = 0.f;

#pragma unroll
  for (int i = 0; i < WT; ++i) {
    // exact-count waits: only real groups are committed
    if (i + PRE < WT) {
      LOAD_STAGE(i + PRE, (i + PRE) % SSTAGES)
      asm volatile("cp.async.wait_group 2;");   // stage i complete
    } else if (i == WT - 2) {
      asm volatile("cp.async.wait_group 1;");   // one group (stage WT-1) left
    } else {                                    // i == WT-1
      asm volatile("cp.async.wait_group 0;");
    }

    const float4* kp = ringw + (i % SSTAGES) * 256 + lane;
    float4 k[8];
#pragma unroll
    for (int p = 0; p < 8; ++p) k[p] = kp[p * 32];

    float s = 0.f;
#pragma unroll
    for (int p = 0; p < 8; ++p)
      s += q[p].x * k[p].x + q[p].y * k[p].y + q[p].z * k[p].z +
           q[p].w * k[p].w;
#pragma unroll
    for (int off = 16; off >= 1; off >>= 1)
      s += __shfl_xor_sync(0xffffffffu, s, off);
    s *= scale;

    if (lane == 0) g_scores[b * TT + t0 + i] = s;

    if (s > m) {  // warp-uniform branch (s identical on all lanes)
      const float r = __expf(m - s);
#pragma unroll
      for (int p = 0; p < 8; ++p) {
        a[p].x *= r; a[p].y *= r; a[p].z *= r; a[p].w *= r;
      }
      l *= r;
      m = s;
    }
    const float w = __expf(s - m);
    l += w;
#pragma unroll
    for (int p = 0; p < 8; ++p) {
      a[p].x += w * k[p].x;
      a[p].y += w * k[p].y;
      a[p].z += w * k[p].z;
      a[p].w += w * k[p].w;
    }
  }
#undef LOAD_STAGE

  // ---- block-level merge of the 4 warps' partials (reuse ring smem) ----
  __shared__ float s_m[4], s_l[4];
  if (lane == 0) { s_m[warp] = m; s_l[warp] = l; }
  __syncthreads();

  const float Mb = fmaxf(fmaxf(s_m[0], s_m[1]), fmaxf(s_m[2], s_m[3]));
  const float Lb = s_l[0] * __expf(s_m[0] - Mb) + s_l[1] * __expf(s_m[1] - Mb) +
                   s_l[2] * __expf(s_m[2] - Mb) + s_l[3] * __expf(s_m[3] - Mb);
  const float wf = __expf(m - Mb);  // warp-uniform rescale factor

  // scaled a -> smem: ring[warp*256 + p*32 + lane] covers d = p*128+lane*4
  float4* mw = ring + warp * 256;
#pragma unroll
  for (int p = 0; p < 8; ++p) {
    float4 v = a[p];
    v.x *= wf; v.y *= wf; v.z *= wf; v.w *= wf;
    mw[p * 32 + lane] = v;
  }
  __syncthreads();

  // cooperative sum of 4 warps' vectors -> one partial per block
  float4* pa4 = (float4*)(g_pa + (size_t)(b * NPART + blockIdx.x) * DH);
#pragma unroll
  for (int r = 0; r < 2; ++r) {
    const int idx = r * 128 + threadIdx.x;  // 0..255 float4s
    const float4 v0 = ring[idx];
    const float4 v1 = ring[256 + idx];
    const float4 v2 = ring[512 + idx];
    const float4 v3 = ring[768 + idx];
    float4 v;
    v.x = v0.x + v1.x + v2.x + v3.x;
    v.y = v0.y + v1.y + v2.y + v3.y;
    v.z = v0.z + v1.z + v2.z + v3.z;
    v.w = v0.w + v1.w + v2.w + v3.w;
    pa4[idx] = v;
  }
  if (threadIdx.x == 0) {
    g_pm[b * NPART + blockIdx.x] = Mb;
    g_pl[b * NPART + blockIdx.x] = Lb;
  }
}

// ---------------------------------------------------------------------------
// Kernel C: combine per-block partials -> attn_values + normalized scores.
// PDL: launches during attn_main, waits at entry (ramp overlapped).
// grid (BB, 8), 128 threads: block handles 128 d's + 256 score elements.
// ---------------------------------------------------------------------------
__global__ __launch_bounds__(128) void combine_kernel(float* __restrict__ out) {
  grid_dep_wait();   // attn_main grid complete; its writes visible

  const int b = blockIdx.x;
  const int ds = blockIdx.y;
  const int j = threadIdx.x;

  __shared__ float sm[NPART], sw[NPART];
  __shared__ float sL;
  if (j < NPART) sm[j] = g_pm[b * NPART + j];
  __syncthreads();

  float M = -1e30f;
#pragma unroll
  for (int w = 0; w < NPART; ++w) M = fmaxf(M, sm[w]);
  if (j < NPART) sw[j] = __expf(sm[j] - M);
  __syncthreads();

  if (j == 0) {
    float L = 0.f;
#pragma unroll
    for (int w = 0; w < NPART; ++w) L += g_pl[b * NPART + w] * sw[w];
    sL = 1.f / L;
  }
  __syncthreads();
  const float invL = sL;

  const int d = ds * 128 + j;
  const float* pa = g_pa + (size_t)b * NPART * DH + d;
  float v0 = 0.f, v1 = 0.f, v2 = 0.f, v3 = 0.f;
#pragma unroll
  for (int w = 0; w < NPART; w += 4) {
    v0 += sw[w + 0] * pa[(size_t)(w + 0) * DH];
    v1 += sw[w + 1] * pa[(size_t)(w + 1) * DH];
    v2 += sw[w + 2] * pa[(size_t)(w + 2) * DH];
    v3 += sw[w + 3] * pa[(size_t)(w + 3) * DH];
  }
  out[b * DH + d] = (v0 + v1 + v2 + v3) * invL;

  // fused scores normalization: this block covers t in [ds*256, ds*256+256)
  const int tb = ds * 256 + j * 2;
  const float2 s2 = *(const float2*)(g_scores + b * TT + tb);
  float2 o2;
  o2.x = __expf(s2.x - M) * invL;
  o2.y = __expf(s2.y - M) * invL;
  *(float2*)(out + BB * DH + b * TT + tb) = o2;
}

// ---------------------------------------------------------------------------
extern "C" void kernel_launch(void* const* d_in, const int* in_sizes, int n_in,
                              void* d_out, int out_size) {
  const float* input = (const float*)d_in[0];   // (32, 1024)
  const float* enc_h = (const float*)d_in[1];   // (2, 2048, 32, 512)
  // d_in[2] decoder_state: unused
  const float* Wq = (const float*)d_in[3];      // (1024, 1024)
  const float* bq = (const float*)d_in[4];      // (1024,)
  // d_in[5] t: unused
  float* out = (float*)d_out;  // [attn_values (32*1024)] ++ [attn_scores (32*2048)]

  const int smem_main = 4 * SSTAGES * 256 * sizeof(float4);  // 48 KB
  const int smem_qp = 4096 * sizeof(float4);                 // 64 KB
  cudaFuncSetAttribute(attn_main_kernel,
                       cudaFuncAttributeMaxDynamicSharedMemorySize, smem_main);
  cudaFuncSetAttribute(qproj_kernel,
                       cudaFuncAttributeMaxDynamicSharedMemorySize, smem_qp);

  qproj_kernel<<<dim3(32, KSPLIT), 256, smem_qp>>>(input, Wq);

  // attn_main with PDL (falls back to a plain launch on error)
  {
    cudaLaunchConfig_t cfg = {};
    cfg.gridDim = dim3(NWARP / 4, BB);
    cfg.blockDim = dim3(128, 1, 1);
    cfg.dynamicSmemBytes = smem_main;
    cfg.stream = 0;
    cudaLaunchAttribute at[1];
    at[0].id = cudaLaunchAttributeProgrammaticStreamSerialization;
    at[0].val.programmaticStreamSerializationAllowed = 1;
    cfg.attrs = at;
    cfg.numAttrs = 1;
    if (cudaLaunchKernelEx(&cfg, attn_main_kernel, enc_h, bq) != cudaSuccess)
      attn_main_kernel<<<dim3(NWARP / 4, BB), 128, smem_main>>>(enc_h, bq);
  }

  // combine with PDL (falls back to a plain launch on error)
  {
    cudaLaunchConfig_t cfg = {};
    cfg.gridDim = dim3(BB, 8);
    cfg.blockDim = dim3(128, 1, 1);
    cfg.dynamicSmemBytes = 0;
    cfg.stream = 0;
    cudaLaunchAttribute at[1];
    at[0].id = cudaLaunchAttributeProgrammaticStreamSerialization;
    at[0].val.programmaticStreamSerializationAllowed = 1;
    cfg.attrs = at;
    cfg.numAttrs = 1;
    if (cudaLaunchKernelEx(&cfg, combine_kernel, out) != cudaSuccess)
      combine_kernel<<<dim3(BB, 8), 128>>>(out);
  }
}